// round 13
// baseline (speedup 1.0000x reference)
#include <cuda_runtime.h>
#include <cuda_bf16.h>
#include <math_constants.h>
#include <cstdint>

#define S_ 16384
#define K_ 4096
#define D_ 64
#define TEMP_ 50.0f
#define MAXEFF_ 5000.0f

// ---------------- scratch ----------------
__device__ float  g_e[(size_t)S_ * K_];        // exp'd (unnormalized) weights
__device__ float  g_zinv[S_];                  // 1/Z per row
// Fragment-packed tf32 splits {hi(t), hi(t+4), lo(t), lo(t+4)}:
__device__ float4 g_Xp[(size_t)S_ * 32];       // [row][d-slab][t]
__device__ float4 g_Yp1[K_ * 32];              // [row][d-slab][t]
__device__ float4 g_Yt2[D_ * (K_ / 8) * 4];    // [d][k-slab][t]
// hi-only Y table for the in-kernel minimax pass:
__device__ float2 g_Yh[K_ * 32];

#define NX  (S_ * 32)
#define NYA (K_ * 32)
#define NYT (D_ * (K_ / 8) * 4)

__device__ __forceinline__ float tf32r(float x) {
    uint32_t u;
    asm("cvt.rna.tf32.f32 %0, %1;" : "=r"(u) : "f"(x));
    return __uint_as_float(u);
}
__device__ __forceinline__ void split1(float x, float& h, float& l) {
    h = tf32r(x);
    l = tf32r(x - h);
}
__device__ __forceinline__ float ex2(float x) {
    float r; asm("ex2.approx.ftz.f32 %0, %1;" : "=f"(r) : "f"(x)); return r;
}
__device__ __forceinline__ void mma8(float* c, const uint32_t* a,
                                     uint32_t b0, uint32_t b1) {
    asm volatile(
        "mma.sync.aligned.m16n8k8.row.col.f32.tf32.tf32.f32 "
        "{%0,%1,%2,%3}, {%4,%5,%6,%7}, {%8,%9}, {%0,%1,%2,%3};"
        : "+f"(c[0]), "+f"(c[1]), "+f"(c[2]), "+f"(c[3])
        : "r"(a[0]), "r"(a[1]), "r"(a[2]), "r"(a[3]), "r"(b0), "r"(b1));
}

// ---------------------------------------------------------------------------
// k_prepX / k_prepY: packed split tables.
// ---------------------------------------------------------------------------
__global__ __launch_bounds__(256) void k_prepX(const float* __restrict__ X) {
    const int i = blockIdx.x * 256 + threadIdx.x;    // < NX
    int r = i >> 5, s = (i >> 2) & 7, t = i & 3;
    float h0, l0, h1, l1;
    split1(X[r * D_ + 8 * s + t],     h0, l0);
    split1(X[r * D_ + 8 * s + t + 4], h1, l1);
    g_Xp[i] = make_float4(h0, h1, l0, l1);
}
__global__ __launch_bounds__(256) void k_prepY(const float* __restrict__ Yw) {
    const int i = blockIdx.x * 256 + threadIdx.x;    // < NYA + NYT
    if (i < NYA) {
        int r = i >> 5, s = (i >> 2) & 7, t = i & 3;
        float h0, l0, h1, l1;
        split1(Yw[r * D_ + 8 * s + t],     h0, l0);
        split1(Yw[r * D_ + 8 * s + t + 4], h1, l1);
        g_Yp1[i] = make_float4(h0, h1, l0, l1);
        g_Yh[i]  = make_float2(h0, h1);
    } else {
        int j = i - NYA;
        int d = j >> 11, s = (j >> 2) & 511, t = j & 3;
        float h0, l0, h1, l1;
        split1(Yw[(8 * s + t) * D_ + d],     h0, l0);
        split1(Yw[(8 * s + t + 4) * D_ + d], h1, l1);
        g_Yt2[j] = make_float4(h0, h1, l0, l1);
    }
}

// ---------------------------------------------------------------------------
// k_gemm_e: per CTA, 64 rows persistent. A staged once.
//  pass 1: stream 64 hi-only B chunks -> 1x MMA -> exact row max/min (regs).
//  pass 2: stream 64 full B chunks -> 3x MMA -> exp -> store e; full Z,v.
// 8 warps = 4 row-groups (16 rows) x 2 col-groups (32 cols). 2 CTA/SM.
// ---------------------------------------------------------------------------
__global__ __launch_bounds__(256, 2) void k_gemm_e(
    const float* __restrict__ icpt, float* __restrict__ out_v)
{
    extern __shared__ float4 sm4[];
    float4* As  = sm4;                     // [64][33]
    float4* Bs  = sm4 + 64 * 33;           // 2 x [64][33] (pass2)
    float2* Bh2 = (float2*)Bs;             // 2 x [64][36] f2 (pass1, aliases Bs)
    float*  redA = (float*)(sm4 + 3 * 64 * 33);  // [128] (mx / z partials)
    float*  redB = redA + 128;                   // [128] (mn / v partials)
    float*  mS_  = redB + 128;                   // [64]
    float*  cS_  = mS_ + 64;                     // [64]

    const int tid = threadIdx.x;
    const int lane = tid & 31, wid = tid >> 5;
    const int kg = wid >> 2;                // col-group 0/1
    const int rb = (wid & 3) * 16;          // row base within 64
    const int g = lane >> 2, t = lane & 3;
    const int r0 = blockIdx.x * 64;
    const int wn = kg * 32;

    // stage A once (64 rows x 32 f4)
    #pragma unroll
    for (int j = 0; j < 8; j++) {
        int f = tid + j * 256;
        int row = f >> 5, w = f & 31;
        As[row * 33 + w] = g_Xp[(size_t)(r0 + row) * 32 + w];
    }

    // ---------------- pass 1: minimax (hi-only, 1x) ----------------
    auto stageBh = [&](int c, int buf) {
        float2* dst = Bh2 + buf * (64 * 36);
        #pragma unroll
        for (int j = 0; j < 8; j++) {
            int f = tid + j * 256;
            int row = f >> 5, w = f & 31;
            dst[row * 36 + w] = __ldg(&g_Yh[(c * 64 + row) * 32 + w]);
        }
    };

    stageBh(0, 0);
    __syncthreads();

    float mx[2] = {-CUDART_INF_F, -CUDART_INF_F};
    float mn[2] = { CUDART_INF_F,  CUDART_INF_F};

    for (int c = 0; c < 64; c++) {
        const int cur = c & 1;
        if (c + 1 < 64) stageBh(c + 1, cur ^ 1);
        const float2* B = Bh2 + cur * (64 * 36);

        float acc[4][4];
        #pragma unroll
        for (int nt = 0; nt < 4; nt++)
            #pragma unroll
            for (int q = 0; q < 4; q++) acc[nt][q] = 0.0f;

        #pragma unroll
        for (int s = 0; s < 8; s++) {
            uint4 q0 = *(const uint4*)&As[(rb + g) * 33 + s * 4 + t];
            uint4 q1 = *(const uint4*)&As[(rb + 8 + g) * 33 + s * 4 + t];
            uint32_t a_[4] = {q0.x, q1.x, q0.y, q1.y};
            #pragma unroll
            for (int nt = 0; nt < 4; nt++) {
                float2 b = B[(wn + nt * 8 + g) * 36 + s * 4 + t];
                mma8(acc[nt], a_, __float_as_uint(b.x), __float_as_uint(b.y));
            }
        }
        #pragma unroll
        for (int nt = 0; nt < 4; nt++) {
            const int cc = c * 64 + wn + nt * 8 + 2 * t;
            float2 ic = __ldg((const float2*)(icpt + cc));
            float o0 = acc[nt][0] - ic.x;
            float o1 = acc[nt][1] - ic.y;
            float o2 = acc[nt][2] - ic.x;
            float o3 = acc[nt][3] - ic.y;
            mx[0] = fmaxf(mx[0], fmaxf(o0, o1));
            mn[0] = fminf(mn[0], fminf(o0, o1));
            mx[1] = fmaxf(mx[1], fmaxf(o2, o3));
            mn[1] = fminf(mn[1], fminf(o2, o3));
        }
        __syncthreads();
    }

    // reduce across t-lanes (quad) then across the 2 col-groups
    #pragma unroll
    for (int m = 1; m < 4; m <<= 1) {
        #pragma unroll
        for (int i = 0; i < 2; i++) {
            mx[i] = fmaxf(mx[i], __shfl_xor_sync(0xffffffffu, mx[i], m));
            mn[i] = fminf(mn[i], __shfl_xor_sync(0xffffffffu, mn[i], m));
        }
    }
    if (t == 0) {
        redA[kg * 64 + rb + g]     = mx[0];
        redA[kg * 64 + rb + 8 + g] = mx[1];
        redB[kg * 64 + rb + g]     = mn[0];
        redB[kg * 64 + rb + 8 + g] = mn[1];
    }
    __syncthreads();
    if (tid < 64) {
        float mxv = fmaxf(redA[tid], redA[64 + tid]);
        float mnv = fminf(redB[tid], redB[64 + tid]);
        float span = fmaxf(mxv - mnv, 1e-3f);
        float tr = fminf(fmaxf(TEMP_ / span, TEMP_), MAXEFF_);
        mS_[tid] = mxv;
        cS_[tid] = tr * 1.4426950408889634f;
    }
    __syncthreads();
    const float mR[2] = {mS_[rb + g], mS_[rb + 8 + g]};
    const float cR[2] = {cS_[rb + g], cS_[rb + 8 + g]};

    // ---------------- pass 2: 3x aff -> exp -> e, Z, v ----------------
    auto stageB = [&](int c, int buf) {
        float4* dst = Bs + buf * (64 * 33);
        #pragma unroll
        for (int j = 0; j < 8; j++) {
            int f = tid + j * 256;
            int row = f >> 5, w = f & 31;
            dst[row * 33 + w] = __ldg(&g_Yp1[(c * 64 + row) * 32 + w]);
        }
    };

    stageB(0, 0);
    float zv[2] = {0, 0}, vv[2] = {0, 0};
    __syncthreads();

    for (int c = 0; c < 64; c++) {
        const int cur = c & 1;
        if (c + 1 < 64) stageB(c + 1, cur ^ 1);
        const float4* B = Bs + cur * (64 * 33);

        float acc[4][4];
        #pragma unroll
        for (int nt = 0; nt < 4; nt++)
            #pragma unroll
            for (int q = 0; q < 4; q++) acc[nt][q] = 0.0f;

        #pragma unroll
        for (int s = 0; s < 8; s++) {
            uint4 q0 = *(const uint4*)&As[(rb + g) * 33 + s * 4 + t];
            uint4 q1 = *(const uint4*)&As[(rb + 8 + g) * 33 + s * 4 + t];
            uint32_t ah[4] = {q0.x, q1.x, q0.y, q1.y};
            uint32_t al[4] = {q0.z, q1.z, q0.w, q1.w};
            #pragma unroll
            for (int nt = 0; nt < 4; nt++) {
                uint4 bq = *(const uint4*)&B[(wn + nt * 8 + g) * 33 + s * 4 + t];
                mma8(acc[nt], ah, bq.x, bq.y);
                mma8(acc[nt], ah, bq.z, bq.w);
                mma8(acc[nt], al, bq.x, bq.y);
            }
        }

        #pragma unroll
        for (int nt = 0; nt < 4; nt++) {
            const int cc = c * 64 + wn + nt * 8 + 2 * t;
            float2 ic = __ldg((const float2*)(icpt + cc));
            const int re = r0 + rb + g;
            float o0 = acc[nt][0] - ic.x;
            float o1 = acc[nt][1] - ic.y;
            float o2 = acc[nt][2] - ic.x;
            float o3 = acc[nt][3] - ic.y;
            float e0 = ex2(fminf((o0 - mR[0]) * cR[0], 8.0f));
            float e1 = ex2(fminf((o1 - mR[0]) * cR[0], 8.0f));
            float e2 = ex2(fminf((o2 - mR[1]) * cR[1], 8.0f));
            float e3 = ex2(fminf((o3 - mR[1]) * cR[1], 8.0f));
            zv[0] += e0 + e1;
            zv[1] += e2 + e3;
            vv[0] = fmaf(e0, o0, fmaf(e1, o1, vv[0]));
            vv[1] = fmaf(e2, o2, fmaf(e3, o3, vv[1]));
            *(float2*)(g_e + (size_t)re * K_ + cc)       = make_float2(e0, e1);
            *(float2*)(g_e + (size_t)(re + 8) * K_ + cc) = make_float2(e2, e3);
        }
        __syncthreads();
    }

    // finalize Z, v (complete per row: CTA owns all K)
    #pragma unroll
    for (int m = 1; m < 4; m <<= 1) {
        #pragma unroll
        for (int i = 0; i < 2; i++) {
            zv[i] += __shfl_xor_sync(0xffffffffu, zv[i], m);
            vv[i] += __shfl_xor_sync(0xffffffffu, vv[i], m);
        }
    }
    if (t == 0) {
        redA[kg * 64 + rb + g]     = zv[0];
        redA[kg * 64 + rb + 8 + g] = zv[1];
        redB[kg * 64 + rb + g]     = vv[0];
        redB[kg * 64 + rb + 8 + g] = vv[1];
    }
    __syncthreads();
    if (tid < 64) {
        float Z = redA[tid] + redA[64 + tid];
        float v = redB[tid] + redB[64 + tid];
        g_zinv[r0 + tid] = 1.0f / Z;
        out_v[r0 + tid] = v / Z;
    }
}

// ---------------------------------------------------------------------------
// k_soft: pure GEMM choice = (e @ Y) * zinv.  64-row CTAs, 2 CTA/SM,
// 256 thr = 4 row-warps x 2 k-groups; double-buffered operand staging.
// ---------------------------------------------------------------------------
__global__ __launch_bounds__(256, 2) void k_soft(float* __restrict__ out_choice)
{
    extern __shared__ float sbf[];
    float*  E  = sbf;                        // 2 x [64][36]
    float4* Yb = (float4*)(sbf + 2 * 64 * 36);   // 2 x [64][20] f4
    float*  Zi = sbf + 2 * 64 * 36 + 2 * 1280 * 4;  // [64]

    const int tid = threadIdx.x;
    const int lane = tid & 31, wid = tid >> 5;
    const int kg = wid >> 2;                 // 0/1
    const int rb = (wid & 3) * 16;           // 16 rows per warp
    const int g = lane >> 2, t = lane & 3;
    const int r0 = blockIdx.x * 64;

    if (tid < 64) Zi[tid] = g_zinv[r0 + tid];

    auto stageE = [&](int ck, int buf) {
        float* dst = E + buf * (64 * 36);
        const float4* src = (const float4*)g_e;
        #pragma unroll
        for (int j = 0; j < 2; j++) {
            int f = tid + j * 256;           // 512 f4
            int row = f >> 3, c4 = f & 7;
            float4 v4 = __ldg(src + (size_t)(r0 + row) * 1024 + ck * 8 + c4);
            *(float4*)&dst[row * 36 + 4 * c4] = v4;
        }
    };
    auto stageY = [&](int ck, int buf) {
        float4* dst = Yb + buf * 1280;
        #pragma unroll
        for (int j = 0; j < 4; j++) {
            int f = tid + j * 256;           // 1024 f4
            int d = f >> 4, w = f & 15;
            dst[d * 20 + w] = __ldg(&g_Yt2[d * 2048 + ck * 16 + w]);
        }
    };

    float acc[8][4];
    #pragma unroll
    for (int nt = 0; nt < 8; nt++)
        #pragma unroll
        for (int q = 0; q < 4; q++) acc[nt][q] = 0.0f;

    stageE(0, 0);
    stageY(0, 0);
    __syncthreads();

    for (int ck = 0; ck < 128; ck++) {
        const int cur = ck & 1;
        if (ck + 1 < 128) {
            stageE(ck + 1, cur ^ 1);
            stageY(ck + 1, cur ^ 1);
        }
        const float*  Ec = E + cur * (64 * 36);
        const float4* Yc = Yb + cur * 1280;

        #pragma unroll
        for (int s = 0; s < 2; s++) {
            const int kcol = kg * 16 + s * 8;
            float e0 = Ec[(rb + g) * 36 + kcol + t];
            float e1 = Ec[(rb + 8 + g) * 36 + kcol + t];
            float e2 = Ec[(rb + g) * 36 + kcol + t + 4];
            float e3 = Ec[(rb + 8 + g) * 36 + kcol + t + 4];
            uint32_t ah[4], al[4];
            float h, l;
            split1(e0, h, l); ah[0] = __float_as_uint(h); al[0] = __float_as_uint(l);
            split1(e1, h, l); ah[1] = __float_as_uint(h); al[1] = __float_as_uint(l);
            split1(e2, h, l); ah[2] = __float_as_uint(h); al[2] = __float_as_uint(l);
            split1(e3, h, l); ah[3] = __float_as_uint(h); al[3] = __float_as_uint(l);
            #pragma unroll
            for (int nt = 0; nt < 8; nt++) {
                uint4 bq = *(const uint4*)&Yc[(nt * 8 + g) * 20 + kg * 8 + s * 4 + t];
                mma8(acc[nt], ah, bq.x, bq.y);
                mma8(acc[nt], ah, bq.z, bq.w);
                mma8(acc[nt], al, bq.x, bq.y);
            }
        }
        __syncthreads();
    }

    // cross-kg reduction through (dead) E-buffer smem
    float* Rch = sbf;                 // [64][66]
    if (kg == 1) {
        #pragma unroll
        for (int nt = 0; nt < 8; nt++) {
            const int col = nt * 8 + 2 * t;
            *(float2*)&Rch[(rb + g) * 66 + col]     = make_float2(acc[nt][0], acc[nt][1]);
            *(float2*)&Rch[(rb + 8 + g) * 66 + col] = make_float2(acc[nt][2], acc[nt][3]);
        }
    }
    __syncthreads();
    if (kg == 0) {
        const float inv0 = Zi[rb + g];
        const float inv1 = Zi[rb + 8 + g];
        #pragma unroll
        for (int nt = 0; nt < 8; nt++) {
            const int col = nt * 8 + 2 * t;
            float2 p0 = *(const float2*)&Rch[(rb + g) * 66 + col];
            float2 p1 = *(const float2*)&Rch[(rb + 8 + g) * 66 + col];
            *(float2*)(out_choice + (size_t)(r0 + rb + g) * D_ + col) =
                make_float2((acc[nt][0] + p0.x) * inv0, (acc[nt][1] + p0.y) * inv0);
            *(float2*)(out_choice + (size_t)(r0 + rb + 8 + g) * D_ + col) =
                make_float2((acc[nt][2] + p1.x) * inv1, (acc[nt][3] + p1.y) * inv1);
        }
    }
}

// ---------------------------------------------------------------------------
extern "C" void kernel_launch(void* const* d_in, const int* in_sizes, int n_in,
                              void* d_out, int out_size) {
    const float* X    = (const float*)d_in[0];
    const float* Yw   = (const float*)d_in[1];
    const float* icpt = (const float*)d_in[2];
    float* out        = (float*)d_out;
    float* out_choice = out;
    float* out_v      = out + (size_t)S_ * D_;

    const int smemG = 3 * 64 * 33 * 16 + 384 * 4;             // 102,912
    const int smemS = (2 * 64 * 36 + 2 * 1280 * 4 + 64) * 4;  // 59,648
    cudaFuncSetAttribute(k_gemm_e, cudaFuncAttributeMaxDynamicSharedMemorySize, smemG);
    cudaFuncSetAttribute(k_soft,   cudaFuncAttributeMaxDynamicSharedMemorySize, smemS);

    k_prepX<<<NX / 256, 256>>>(X);                          // launch 0
    k_prepY<<<(NYA + NYT) / 256, 256>>>(Yw);                // launch 1
    k_gemm_e<<<S_ / 64, 256, smemG>>>(icpt, out_v);         // launch 2
    k_soft<<<S_ / 64, 256, smemS>>>(out_choice);            // launch 3  <- ncu
}

// round 14
// speedup vs baseline: 1.2994x; 1.2994x over previous
#include <cuda_runtime.h>
#include <cuda_bf16.h>
#include <math_constants.h>
#include <cstdint>

#define S_ 16384
#define K_ 4096
#define D_ 64
#define TEMP_ 50.0f
#define MAXEFF_ 5000.0f

// ---------------- scratch ----------------
__device__ float        g_aff[(size_t)S_ * K_];
__device__ unsigned int g_pmax[S_];   // max enc(aff); 0 == -inf (no init needed)
__device__ unsigned int g_nmax[S_];   // max enc(-aff)
// Fragment-packed tf32 splits {hi(t), hi(t+4), lo(t), lo(t+4)}:
__device__ float4 g_Xp[(size_t)S_ * 32];    // [row][d-slab][t]
__device__ float4 g_Yp1[K_ * 32];           // [row][d-slab][t]
__device__ float4 g_Yt2[D_ * (K_ / 8) * 4]; // [d][k-slab][t]

#define NX  (S_ * 32)
#define NYA (K_ * 32)
#define NYT (D_ * (K_ / 8) * 4)

__device__ __forceinline__ unsigned int encf(float f) {
    unsigned int u = __float_as_uint(f);
    return (u & 0x80000000u) ? ~u : (u | 0x80000000u);
}
__device__ __forceinline__ float decf(unsigned int u) {
    return (u & 0x80000000u) ? __uint_as_float(u ^ 0x80000000u)
                             : __uint_as_float(~u);
}
__device__ __forceinline__ float tf32r(float x) {
    uint32_t u;
    asm("cvt.rna.tf32.f32 %0, %1;" : "=r"(u) : "f"(x));
    return __uint_as_float(u);
}
__device__ __forceinline__ void split1(float x, float& h, float& l) {
    h = tf32r(x);
    l = tf32r(x - h);
}
__device__ __forceinline__ float ex2(float x) {
    float r; asm("ex2.approx.ftz.f32 %0, %1;" : "=f"(r) : "f"(x)); return r;
}
__device__ __forceinline__ void mma8(float* c, const uint32_t* a,
                                     uint32_t b0, uint32_t b1) {
    asm volatile(
        "mma.sync.aligned.m16n8k8.row.col.f32.tf32.tf32.f32 "
        "{%0,%1,%2,%3}, {%4,%5,%6,%7}, {%8,%9}, {%0,%1,%2,%3};"
        : "+f"(c[0]), "+f"(c[1]), "+f"(c[2]), "+f"(c[3])
        : "r"(a[0]), "r"(a[1]), "r"(a[2]), "r"(a[3]), "r"(b0), "r"(b1));
}

// ---------------------------------------------------------------------------
// k_prepX / k_prepY: packed split tables.
// ---------------------------------------------------------------------------
__global__ __launch_bounds__(256) void k_prepX(const float* __restrict__ X) {
    const int i = blockIdx.x * 256 + threadIdx.x;    // < NX
    int r = i >> 5, s = (i >> 2) & 7, t = i & 3;
    float h0, l0, h1, l1;
    split1(X[r * D_ + 8 * s + t],     h0, l0);
    split1(X[r * D_ + 8 * s + t + 4], h1, l1);
    g_Xp[i] = make_float4(h0, h1, l0, l1);
}
__global__ __launch_bounds__(256) void k_prepY(const float* __restrict__ Yw) {
    const int i = blockIdx.x * 256 + threadIdx.x;    // < NYA + NYT
    if (i < NYA) {
        int r = i >> 5, s = (i >> 2) & 7, t = i & 3;
        float h0, l0, h1, l1;
        split1(Yw[r * D_ + 8 * s + t],     h0, l0);
        split1(Yw[r * D_ + 8 * s + t + 4], h1, l1);
        g_Yp1[i] = make_float4(h0, h1, l0, l1);
    } else {
        int j = i - NYA;
        int d = j >> 11, s = (j >> 2) & 511, t = j & 3;
        float h0, l0, h1, l1;
        split1(Yw[(8 * s + t) * D_ + d],     h0, l0);
        split1(Yw[(8 * s + t + 4) * D_ + d], h1, l1);
        g_Yt2[j] = make_float4(h0, h1, l0, l1);
    }
}

// ---------------------------------------------------------------------------
// GEMM1 (R8-verbatim): aff = X @ Y^T - icpt. CTA 128x128, 256 thr.
// Pure-copy staging of both operands; inner loop is LDS + mma only.
// ---------------------------------------------------------------------------
__global__ __launch_bounds__(256, 1) void k_gemm1_tc(const float* __restrict__ icpt)
{
    extern __shared__ float4 sm4[];
    float4* As = sm4;                 // [128][36]
    float4* Bs = sm4 + 128 * 36;      // [128][36]

    const int tid = threadIdx.x;
    const int lane = tid & 31, wid = tid >> 5;
    const int wrow = (wid & 3) * 32;
    const int wn = (wid >> 2) * 64;
    const int g = lane >> 2, t = lane & 3;
    const int r0 = blockIdx.y * 128, c0 = blockIdx.x * 128;

    #pragma unroll
    for (int j = 0; j < 16; j++) {
        int f = tid + j * 256;
        int row = f >> 5, w = f & 31;
        As[row * 36 + w] = g_Xp[(size_t)(r0 + row) * 32 + w];
        Bs[row * 36 + w] = g_Yp1[(c0 + row) * 32 + w];
    }
    __syncthreads();

    float acc[2][8][4];
    #pragma unroll
    for (int mt = 0; mt < 2; mt++)
        #pragma unroll
        for (int nt = 0; nt < 8; nt++)
            #pragma unroll
            for (int q = 0; q < 4; q++) acc[mt][nt][q] = 0.0f;

    #pragma unroll
    for (int s = 0; s < 8; s++) {
        uint32_t ah[2][4], al[2][4];
        #pragma unroll
        for (int mt = 0; mt < 2; mt++) {
            const int rb = wrow + mt * 16;
            uint4 q0 = *(const uint4*)&As[(rb + g) * 36 + s * 4 + t];
            uint4 q1 = *(const uint4*)&As[(rb + 8 + g) * 36 + s * 4 + t];
            ah[mt][0] = q0.x; ah[mt][1] = q1.x; ah[mt][2] = q0.y; ah[mt][3] = q1.y;
            al[mt][0] = q0.z; al[mt][1] = q1.z; al[mt][2] = q0.w; al[mt][3] = q1.w;
        }
        #pragma unroll
        for (int nt = 0; nt < 8; nt++) {
            uint4 bq = *(const uint4*)&Bs[(wn + nt * 8 + g) * 36 + s * 4 + t];
            #pragma unroll
            for (int mt = 0; mt < 2; mt++) {
                mma8(acc[mt][nt], ah[mt], bq.x, bq.y);
                mma8(acc[mt][nt], ah[mt], bq.z, bq.w);
                mma8(acc[mt][nt], al[mt], bq.x, bq.y);
            }
        }
    }

    // epilogue: -icpt, store aff, per-row max/min
    float mx[4] = {-CUDART_INF_F, -CUDART_INF_F, -CUDART_INF_F, -CUDART_INF_F};
    float mn[4] = { CUDART_INF_F,  CUDART_INF_F,  CUDART_INF_F,  CUDART_INF_F};

    #pragma unroll
    for (int mt = 0; mt < 2; mt++) {
        #pragma unroll
        for (int nt = 0; nt < 8; nt++) {
            const int c = c0 + wn + nt * 8 + 2 * t;
            float2 ic = __ldg((const float2*)(icpt + c));
            float o0 = acc[mt][nt][0] - ic.x;
            float o1 = acc[mt][nt][1] - ic.y;
            float o2 = acc[mt][nt][2] - ic.x;
            float o3 = acc[mt][nt][3] - ic.y;
            const int row = r0 + wrow + mt * 16 + g;
            *(float2*)(g_aff + (size_t)row * K_ + c)       = make_float2(o0, o1);
            *(float2*)(g_aff + (size_t)(row + 8) * K_ + c) = make_float2(o2, o3);
            mx[mt*2]   = fmaxf(mx[mt*2],   fmaxf(o0, o1));
            mn[mt*2]   = fminf(mn[mt*2],   fminf(o0, o1));
            mx[mt*2+1] = fmaxf(mx[mt*2+1], fmaxf(o2, o3));
            mn[mt*2+1] = fminf(mn[mt*2+1], fminf(o2, o3));
        }
    }
    #pragma unroll
    for (int m = 1; m < 4; m <<= 1) {
        #pragma unroll
        for (int i = 0; i < 4; i++) {
            mx[i] = fmaxf(mx[i], __shfl_xor_sync(0xffffffffu, mx[i], m));
            mn[i] = fminf(mn[i], __shfl_xor_sync(0xffffffffu, mn[i], m));
        }
    }
    if (t == 0) {
        #pragma unroll
        for (int mt = 0; mt < 2; mt++) {
            const int row = r0 + wrow + mt * 16 + g;
            atomicMax(&g_pmax[row],     encf(mx[mt*2]));
            atomicMax(&g_nmax[row],     encf(-mn[mt*2]));
            atomicMax(&g_pmax[row + 8], encf(mx[mt*2+1]));
            atomicMax(&g_nmax[row + 8], encf(-mn[mt*2+1]));
        }
    }
}

// ---------------------------------------------------------------------------
// k_soft: adaptive softmax + v + choice = w @ Y.
// 32-row CTAs (grid 512), 256 thr = 4 k-groups x 2 row-warps, 2 CTA/SM.
// Y streamed in 16-k chunks (8 buffers); aff LDG + exp + split in registers
// with 1-step prefetch; z/v/choice reduced across k-groups via smem.
// ---------------------------------------------------------------------------
__global__ __launch_bounds__(256, 2) void k_soft(
    float* __restrict__ out_choice, float* __restrict__ out_v)
{
    extern __shared__ float4 sb4[];   // 8 bufs x [64 d][10 f4]  (= 81,920 B)
    float* Zp = (float*)(sb4 + 8 * 640);   // [4][32]
    float* Vp = Zp + 128;                  // [4][32]

    const int tid = threadIdx.x;
    const int lane = tid & 31, wid = tid >> 5;
    const int kg = wid >> 1;              // k-group 0..3
    const int rb = (wid & 1) * 16;        // row base within 32
    const int g = lane >> 2, t = lane & 3;
    const int r0 = blockIdx.x * 32;

    // per-thread row params (2 slots: rows rb+g, rb+8+g)
    float mr[2], c1r[2];
    #pragma unroll
    for (int i = 0; i < 2; i++) {
        const int row = r0 + rb + g + 8 * i;
        float mxv = decf(g_pmax[row]);
        float mnv = -decf(g_nmax[row]);
        float span = fmaxf(mxv - mnv, 1e-3f);
        float tr = fminf(fmaxf(TEMP_ / span, TEMP_), MAXEFF_);
        c1r[i] = tr * 1.4426950408889634f;
        mr[i] = mxv;
    }

    float acc[8][4];
    #pragma unroll
    for (int nt = 0; nt < 8; nt++)
        #pragma unroll
        for (int q = 0; q < 4; q++) acc[nt][q] = 0.0f;
    float zv[2] = {0, 0}, vv[2] = {0, 0};

    // stage round R: 4 chunks (16 k each), chunk for group b is 4R+b
    auto stage = [&](int R, int par) {
        #pragma unroll
        for (int j = 0; j < 8; j++) {
            int f = tid + j * 256;        // 0..2047
            int b = f >> 9, r = f & 511;
            int d = r >> 3, w = r & 7;
            sb4[(b * 2 + par) * 640 + d * 10 + w] =
                __ldg(&g_Yt2[d * 2048 + (4 * R + b) * 8 + w]);
        }
    };

    // aff fragment load for this group's step 0..127 (8 k per step)
    auto ldx = [&](int gstep, float* xa) {
        const int c = 4 * (gstep >> 1) + kg;
        const int kk = c * 16 + (gstep & 1) * 8;
        const float* a0 = g_aff + (size_t)(r0 + rb + g) * K_ + kk;
        const float* a1 = a0 + (size_t)8 * K_;
        xa[0] = __ldg(a0 + t);
        xa[1] = __ldg(a1 + t);
        xa[2] = __ldg(a0 + t + 4);
        xa[3] = __ldg(a1 + t + 4);
    };

    stage(0, 0);
    float xa[4], xb[4];
    ldx(0, xa);
    __syncthreads();

    for (int R = 0; R < 64; R++) {
        const int par = R & 1;
        if (R + 1 < 64) stage(R + 1, par ^ 1);
        const float4* B = sb4 + (kg * 2 + par) * 640;

        #pragma unroll
        for (int s = 0; s < 2; s++) {
            const int gstep = R * 2 + s;
            if (gstep + 1 < 128) ldx(gstep + 1, xb);

            uint32_t ah[4], al[4];
            #pragma unroll
            for (int j = 0; j < 4; j++) {
                const int ri = j & 1;
                float x = xa[j];
                float e = ex2(fminf((x - mr[ri]) * c1r[ri], 8.0f));
                zv[ri] += e;
                vv[ri] = fmaf(e, x, vv[ri]);
                float h, l;
                split1(e, h, l);
                ah[j] = __float_as_uint(h);
                al[j] = __float_as_uint(l);
            }
            #pragma unroll
            for (int nt = 0; nt < 8; nt++) {
                uint4 bq = *(const uint4*)&B[(nt * 8 + g) * 10 + s * 4 + t];
                mma8(acc[nt], ah, bq.x, bq.y);
                mma8(acc[nt], ah, bq.z, bq.w);
                mma8(acc[nt], al, bq.x, bq.y);
            }
            #pragma unroll
            for (int j = 0; j < 4; j++) xa[j] = xb[j];
        }
        __syncthreads();
    }

    // z/v: butterfly over the 4 t-lanes, park per-group partials in smem
    #pragma unroll
    for (int m = 1; m < 4; m <<= 1) {
        #pragma unroll
        for (int i = 0; i < 2; i++) {
            zv[i] += __shfl_xor_sync(0xffffffffu, zv[i], m);
            vv[i] += __shfl_xor_sync(0xffffffffu, vv[i], m);
        }
    }
    if (t == 0) {
        #pragma unroll
        for (int i = 0; i < 2; i++) {
            Zp[kg * 32 + rb + g + 8 * i] = zv[i];
            Vp[kg * 32 + rb + g + 8 * i] = vv[i];
        }
    }

    // choice: groups 1-3 park acc in (dead) buffer smem, group 0 reduces
    float* Rch = (float*)sb4;             // 3 x [32][66] = 25,344 B < 81,920
    if (kg > 0) {
        float* Rg = Rch + (kg - 1) * 32 * 66;
        #pragma unroll
        for (int nt = 0; nt < 8; nt++) {
            const int col = nt * 8 + 2 * t;
            *(float2*)&Rg[(rb + g) * 66 + col]     = make_float2(acc[nt][0], acc[nt][1]);
            *(float2*)&Rg[(rb + 8 + g) * 66 + col] = make_float2(acc[nt][2], acc[nt][3]);
        }
    }
    __syncthreads();

    if (kg == 0) {
        float inv[2];
        #pragma unroll
        for (int i = 0; i < 2; i++) {
            const int row = rb + g + 8 * i;
            float Z = Zp[row] + Zp[32 + row] + Zp[64 + row] + Zp[96 + row];
            inv[i] = 1.0f / Z;
            if (t == 0)
                out_v[r0 + row] =
                    (Vp[row] + Vp[32 + row] + Vp[64 + row] + Vp[96 + row]) / Z;
        }
        #pragma unroll
        for (int nt = 0; nt < 8; nt++) {
            const int col = nt * 8 + 2 * t;
            float s0 = acc[nt][0], s1 = acc[nt][1];
            float s2 = acc[nt][2], s3 = acc[nt][3];
            #pragma unroll
            for (int pg = 0; pg < 3; pg++) {
                const float* Rg = Rch + pg * 32 * 66;
                float2 p0 = *(const float2*)&Rg[(rb + g) * 66 + col];
                float2 p1 = *(const float2*)&Rg[(rb + 8 + g) * 66 + col];
                s0 += p0.x; s1 += p0.y; s2 += p1.x; s3 += p1.y;
            }
            *(float2*)(out_choice + (size_t)(r0 + rb + g) * D_ + col) =
                make_float2(s0 * inv[0], s1 * inv[0]);
            *(float2*)(out_choice + (size_t)(r0 + rb + 8 + g) * D_ + col) =
                make_float2(s2 * inv[1], s3 * inv[1]);
        }
    }
}

// ---------------------------------------------------------------------------
extern "C" void kernel_launch(void* const* d_in, const int* in_sizes, int n_in,
                              void* d_out, int out_size) {
    const float* X    = (const float*)d_in[0];
    const float* Yw   = (const float*)d_in[1];
    const float* icpt = (const float*)d_in[2];
    float* out        = (float*)d_out;
    float* out_choice = out;
    float* out_v      = out + (size_t)S_ * D_;

    const int smemG = 2 * 128 * 36 * 16;          // 147,456
    const int smemS = 8 * 640 * 16 + 256 * 4;     // 82,944
    cudaFuncSetAttribute(k_gemm1_tc, cudaFuncAttributeMaxDynamicSharedMemorySize, smemG);
    cudaFuncSetAttribute(k_soft,     cudaFuncAttributeMaxDynamicSharedMemorySize, smemS);

    k_prepX<<<NX / 256, 256>>>(X);                          // launch 0
    k_prepY<<<(NYA + NYT) / 256, 256>>>(Yw);                // launch 1

    dim3 g1(K_ / 128, S_ / 128);
    k_gemm1_tc<<<g1, 256, smemG>>>(icpt);                   // launch 2
    k_soft<<<S_ / 32, 256, smemS>>>(out_choice, out_v);     // launch 3  <- ncu
}

// round 15
// speedup vs baseline: 1.4268x; 1.0980x over previous
#include <cuda_runtime.h>
#include <cuda_bf16.h>
#include <math_constants.h>
#include <cstdint>

#define S_ 16384
#define K_ 4096
#define D_ 64
#define TEMP_ 50.0f
#define MAXEFF_ 5000.0f

// ---------------- scratch ----------------
// aff in A-fragment-packed layout: [rb=S/16][cb=K/8][lane] float4,
// lane(g,t) holds {(16rb+g,8cb+t),(+8,t),(g,t+4),(+8,t+4)}.
__device__ float4       g_affp[(size_t)(S_ / 16) * (K_ / 8) * 32];
__device__ unsigned int g_pmax[S_];   // max enc(aff); 0 == -inf (no init needed)
__device__ unsigned int g_nmax[S_];   // max enc(-aff)
// Fragment-packed tf32 splits {hi(t), hi(t+4), lo(t), lo(t+4)}:
__device__ float4 g_Xp[(size_t)S_ * 32];    // [row][d-slab][t]
__device__ float4 g_Yp1[K_ * 32];           // [row][d-slab][t]
__device__ float4 g_Yt2[D_ * (K_ / 8) * 4]; // [d][k-slab][t]

#define NX  (S_ * 32)
#define NYA (K_ * 32)
#define NYT (D_ * (K_ / 8) * 4)

__device__ __forceinline__ unsigned int encf(float f) {
    unsigned int u = __float_as_uint(f);
    return (u & 0x80000000u) ? ~u : (u | 0x80000000u);
}
__device__ __forceinline__ float decf(unsigned int u) {
    return (u & 0x80000000u) ? __uint_as_float(u ^ 0x80000000u)
                             : __uint_as_float(~u);
}
__device__ __forceinline__ float tf32r(float x) {
    uint32_t u;
    asm("cvt.rna.tf32.f32 %0, %1;" : "=r"(u) : "f"(x));
    return __uint_as_float(u);
}
__device__ __forceinline__ void split1(float x, float& h, float& l) {
    h = tf32r(x);
    l = tf32r(x - h);
}
__device__ __forceinline__ float ex2(float x) {
    float r; asm("ex2.approx.ftz.f32 %0, %1;" : "=f"(r) : "f"(x)); return r;
}
__device__ __forceinline__ void mma8(float* c, const uint32_t* a,
                                     uint32_t b0, uint32_t b1) {
    asm volatile(
        "mma.sync.aligned.m16n8k8.row.col.f32.tf32.tf32.f32 "
        "{%0,%1,%2,%3}, {%4,%5,%6,%7}, {%8,%9}, {%0,%1,%2,%3};"
        : "+f"(c[0]), "+f"(c[1]), "+f"(c[2]), "+f"(c[3])
        : "r"(a[0]), "r"(a[1]), "r"(a[2]), "r"(a[3]), "r"(b0), "r"(b1));
}

// ---------------------------------------------------------------------------
// k_prepX / k_prepY: packed split tables.
// ---------------------------------------------------------------------------
__global__ __launch_bounds__(256) void k_prepX(const float* __restrict__ X) {
    const int i = blockIdx.x * 256 + threadIdx.x;    // < NX
    int r = i >> 5, s = (i >> 2) & 7, t = i & 3;
    float h0, l0, h1, l1;
    split1(X[r * D_ + 8 * s + t],     h0, l0);
    split1(X[r * D_ + 8 * s + t + 4], h1, l1);
    g_Xp[i] = make_float4(h0, h1, l0, l1);
}
__global__ __launch_bounds__(256) void k_prepY(const float* __restrict__ Yw) {
    const int i = blockIdx.x * 256 + threadIdx.x;    // < NYA + NYT
    if (i < NYA) {
        int r = i >> 5, s = (i >> 2) & 7, t = i & 3;
        float h0, l0, h1, l1;
        split1(Yw[r * D_ + 8 * s + t],     h0, l0);
        split1(Yw[r * D_ + 8 * s + t + 4], h1, l1);
        g_Yp1[i] = make_float4(h0, h1, l0, l1);
    } else {
        int j = i - NYA;
        int d = j >> 11, s = (j >> 2) & 511, t = j & 3;
        float h0, l0, h1, l1;
        split1(Yw[(8 * s + t) * D_ + d],     h0, l0);
        split1(Yw[(8 * s + t + 4) * D_ + d], h1, l1);
        g_Yt2[j] = make_float4(h0, h1, l0, l1);
    }
}

// ---------------------------------------------------------------------------
// GEMM1: aff = X @ Y^T - icpt.  CTA 128x128, 256 thr (R8 core).
// Epilogue: minimax atomics + smem transpose -> fragment-packed g_affp.
// ---------------------------------------------------------------------------
__global__ __launch_bounds__(256, 1) void k_gemm1_tc(const float* __restrict__ icpt)
{
    extern __shared__ float4 sm4[];
    float4* As = sm4;                 // [128][36]
    float4* Bs = sm4 + 128 * 36;      // [128][36]

    const int tid = threadIdx.x;
    const int lane = tid & 31, wid = tid >> 5;
    const int wrow = (wid & 3) * 32;
    const int wn = (wid >> 2) * 64;
    const int g = lane >> 2, t = lane & 3;
    const int r0 = blockIdx.y * 128, c0 = blockIdx.x * 128;

    #pragma unroll
    for (int j = 0; j < 16; j++) {
        int f = tid + j * 256;
        int row = f >> 5, w = f & 31;
        As[row * 36 + w] = g_Xp[(size_t)(r0 + row) * 32 + w];
        Bs[row * 36 + w] = g_Yp1[(c0 + row) * 32 + w];
    }
    __syncthreads();

    float acc[2][8][4];
    #pragma unroll
    for (int mt = 0; mt < 2; mt++)
        #pragma unroll
        for (int nt = 0; nt < 8; nt++)
            #pragma unroll
            for (int q = 0; q < 4; q++) acc[mt][nt][q] = 0.0f;

    #pragma unroll
    for (int s = 0; s < 8; s++) {
        uint32_t ah[2][4], al[2][4];
        #pragma unroll
        for (int mt = 0; mt < 2; mt++) {
            const int rb = wrow + mt * 16;
            uint4 q0 = *(const uint4*)&As[(rb + g) * 36 + s * 4 + t];
            uint4 q1 = *(const uint4*)&As[(rb + 8 + g) * 36 + s * 4 + t];
            ah[mt][0] = q0.x; ah[mt][1] = q1.x; ah[mt][2] = q0.y; ah[mt][3] = q1.y;
            al[mt][0] = q0.z; al[mt][1] = q1.z; al[mt][2] = q0.w; al[mt][3] = q1.w;
        }
        #pragma unroll
        for (int nt = 0; nt < 8; nt++) {
            uint4 bq = *(const uint4*)&Bs[(wn + nt * 8 + g) * 36 + s * 4 + t];
            #pragma unroll
            for (int mt = 0; mt < 2; mt++) {
                mma8(acc[mt][nt], ah[mt], bq.x, bq.y);
                mma8(acc[mt][nt], ah[mt], bq.z, bq.w);
                mma8(acc[mt][nt], al[mt], bq.x, bq.y);
            }
        }
    }
    __syncthreads();   // operand buffers dead; reuse for transpose

    // epilogue: -icpt, minimax, STS to scalar grid T[128][132]
    float* T = (float*)sm4;
    float mx[4] = {-CUDART_INF_F, -CUDART_INF_F, -CUDART_INF_F, -CUDART_INF_F};
    float mn[4] = { CUDART_INF_F,  CUDART_INF_F,  CUDART_INF_F,  CUDART_INF_F};

    #pragma unroll
    for (int mt = 0; mt < 2; mt++) {
        #pragma unroll
        for (int nt = 0; nt < 8; nt++) {
            const int c = wn + nt * 8 + 2 * t;
            float2 ic = __ldg((const float2*)(icpt + c0 + c));
            float o0 = acc[mt][nt][0] - ic.x;
            float o1 = acc[mt][nt][1] - ic.y;
            float o2 = acc[mt][nt][2] - ic.x;
            float o3 = acc[mt][nt][3] - ic.y;
            const int rr = wrow + mt * 16 + g;
            *(float2*)&T[rr * 132 + c]       = make_float2(o0, o1);
            *(float2*)&T[(rr + 8) * 132 + c] = make_float2(o2, o3);
            mx[mt*2]   = fmaxf(mx[mt*2],   fmaxf(o0, o1));
            mn[mt*2]   = fminf(mn[mt*2],   fminf(o0, o1));
            mx[mt*2+1] = fmaxf(mx[mt*2+1], fmaxf(o2, o3));
            mn[mt*2+1] = fminf(mn[mt*2+1], fminf(o2, o3));
        }
    }
    #pragma unroll
    for (int m = 1; m < 4; m <<= 1) {
        #pragma unroll
        for (int i = 0; i < 4; i++) {
            mx[i] = fmaxf(mx[i], __shfl_xor_sync(0xffffffffu, mx[i], m));
            mn[i] = fminf(mn[i], __shfl_xor_sync(0xffffffffu, mn[i], m));
        }
    }
    if (t == 0) {
        #pragma unroll
        for (int mt = 0; mt < 2; mt++) {
            const int row = r0 + wrow + mt * 16 + g;
            atomicMax(&g_pmax[row],     encf(mx[mt*2]));
            atomicMax(&g_nmax[row],     encf(-mn[mt*2]));
            atomicMax(&g_pmax[row + 8], encf(mx[mt*2+1]));
            atomicMax(&g_nmax[row + 8], encf(-mn[mt*2+1]));
        }
    }
    __syncthreads();

    // fragment-packed store: each warp handles one 16x8 block per iteration
    const int rb0 = blockIdx.y * 8, cb0 = blockIdx.x * 16;
    #pragma unroll
    for (int j = 0; j < 16; j++) {
        int f = tid + j * 256;
        int ln = f & 31, blk = f >> 5;         // blk 0..127
        int rb = blk >> 4, cb = blk & 15;
        int gp = ln >> 2, tp = ln & 3;
        int rr = rb * 16 + gp, cc = cb * 8 + tp;
        float4 o;
        o.x = T[rr * 132 + cc];
        o.y = T[(rr + 8) * 132 + cc];
        o.z = T[rr * 132 + cc + 4];
        o.w = T[(rr + 8) * 132 + cc + 4];
        g_affp[((size_t)(rb0 + rb) * (K_ / 8) + cb0 + cb) * 32 + ln] = o;
    }
}

// ---------------------------------------------------------------------------
// k_soft: adaptive softmax + v + choice = w @ Y.
// 64-row CTAs (grid 256, 2 CTA/SM), 256 thr = 4 k-groups x 2 row-warps
// (32 rows/warp, mt=2 -> B frag reused 2x). A path: ONE coalesced LDG.128
// per mt per 8-k step from g_affp, exp+split in regs, 1-step prefetch.
// ---------------------------------------------------------------------------
__global__ __launch_bounds__(256, 2) void k_soft(
    float* __restrict__ out_choice, float* __restrict__ out_v)
{
    extern __shared__ float4 sb4[];   // 8 bufs x [64 d][10 f4]  (81,920 B)
    float* Zp = (float*)(sb4 + 8 * 640);   // [4][64]
    float* Vp = Zp + 256;                  // [4][64]

    const int tid = threadIdx.x;
    const int lane = tid & 31, wid = tid >> 5;
    const int kg = wid >> 1;              // k-group 0..3
    const int mw = wid & 1;               // row-warp: rows 32*mw..
    const int g = lane >> 2, t = lane & 3;
    const int r0 = blockIdx.x * 64;
    const int rbase = (r0 >> 4) + 2 * mw; // global rb for mt=0

    // per-thread row params: slot mt*2+i -> row 32mw+16mt+g+8i
    float mr[4], cr[4];
    #pragma unroll
    for (int mt = 0; mt < 2; mt++)
        #pragma unroll
        for (int i = 0; i < 2; i++) {
            const int row = r0 + 32 * mw + 16 * mt + g + 8 * i;
            float mxv = decf(g_pmax[row]);
            float mnv = -decf(g_nmax[row]);
            float span = fmaxf(mxv - mnv, 1e-3f);
            float tr = fminf(fmaxf(TEMP_ / span, TEMP_), MAXEFF_);
            cr[mt*2+i] = tr * 1.4426950408889634f;
            mr[mt*2+i] = mxv;
        }

    float acc[2][8][4];
    #pragma unroll
    for (int mt = 0; mt < 2; mt++)
        #pragma unroll
        for (int nt = 0; nt < 8; nt++)
            #pragma unroll
            for (int q = 0; q < 4; q++) acc[mt][nt][q] = 0.0f;
    float zv[4] = {0, 0, 0, 0}, vv[4] = {0, 0, 0, 0};

    // stage round R: 4 chunks (16 k), chunk for group b is 4R+b
    auto stage = [&](int R, int par) {
        #pragma unroll
        for (int j = 0; j < 8; j++) {
            int f = tid + j * 256;        // 0..2047
            int b = f >> 9, r = f & 511;
            int d = r >> 3, w = r & 7;
            sb4[(b * 2 + par) * 640 + d * 10 + w] =
                __ldg(&g_Yt2[d * 2048 + (4 * R + b) * 8 + w]);
        }
    };

    // coalesced A-frag load: gstep 0..127 (8 k each)
    auto ldx = [&](int gstep, float4* xa) {
        const int c = 4 * (gstep >> 1) + kg;       // 16-k chunk 0..255
        const int cb = c * 2 + (gstep & 1);        // 8-col block 0..511
        #pragma unroll
        for (int mt = 0; mt < 2; mt++)
            xa[mt] = __ldg(&g_affp[((size_t)(rbase + mt) * (K_ / 8) + cb) * 32 + lane]);
    };

    stage(0, 0);
    float4 xa[2], xb[2];
    ldx(0, xa);
    __syncthreads();

    for (int R = 0; R < 64; R++) {
        const int par = R & 1;
        if (R + 1 < 64) stage(R + 1, par ^ 1);
        const float4* B = sb4 + (kg * 2 + par) * 640;

        #pragma unroll
        for (int s = 0; s < 2; s++) {
            const int gstep = R * 2 + s;
            if (gstep + 1 < 128) ldx(gstep + 1, xb);

            uint32_t ah[2][4], al[2][4];
            #pragma unroll
            for (int mt = 0; mt < 2; mt++) {
                float4 x = xa[mt];
                // frag order: x=(g,t), y=(g+8,t), z=(g,t+4), w=(g+8,t+4)
                float e0 = ex2(fminf((x.x - mr[mt*2])   * cr[mt*2],   8.0f));
                float e1 = ex2(fminf((x.y - mr[mt*2+1]) * cr[mt*2+1], 8.0f));
                float e2 = ex2(fminf((x.z - mr[mt*2])   * cr[mt*2],   8.0f));
                float e3 = ex2(fminf((x.w - mr[mt*2+1]) * cr[mt*2+1], 8.0f));
                zv[mt*2]   += e0 + e2;
                zv[mt*2+1] += e1 + e3;
                vv[mt*2]   = fmaf(e0, x.x, fmaf(e2, x.z, vv[mt*2]));
                vv[mt*2+1] = fmaf(e1, x.y, fmaf(e3, x.w, vv[mt*2+1]));
                float h, l;
                split1(e0, h, l); ah[mt][0] = __float_as_uint(h); al[mt][0] = __float_as_uint(l);
                split1(e1, h, l); ah[mt][1] = __float_as_uint(h); al[mt][1] = __float_as_uint(l);
                split1(e2, h, l); ah[mt][2] = __float_as_uint(h); al[mt][2] = __float_as_uint(l);
                split1(e3, h, l); ah[mt][3] = __float_as_uint(h); al[mt][3] = __float_as_uint(l);
            }
            #pragma unroll
            for (int nt = 0; nt < 8; nt++) {
                uint4 bq = *(const uint4*)&B[(nt * 8 + g) * 10 + s * 4 + t];
                #pragma unroll
                for (int mt = 0; mt < 2; mt++) {
                    mma8(acc[mt][nt], ah[mt], bq.x, bq.y);
                    mma8(acc[mt][nt], ah[mt], bq.z, bq.w);
                    mma8(acc[mt][nt], al[mt], bq.x, bq.y);
                }
            }
            xa[0] = xb[0]; xa[1] = xb[1];
        }
        __syncthreads();
    }

    // z/v: butterfly over the 4 t-lanes, park per-group partials
    #pragma unroll
    for (int m = 1; m < 4; m <<= 1) {
        #pragma unroll
        for (int i = 0; i < 4; i++) {
            zv[i] += __shfl_xor_sync(0xffffffffu, zv[i], m);
            vv[i] += __shfl_xor_sync(0xffffffffu, vv[i], m);
        }
    }
    if (t == 0) {
        #pragma unroll
        for (int mt = 0; mt < 2; mt++)
            #pragma unroll
            for (int i = 0; i < 2; i++) {
                const int row = 32 * mw + 16 * mt + g + 8 * i;
                Zp[kg * 64 + row] = zv[mt*2+i];
                Vp[kg * 64 + row] = vv[mt*2+i];
            }
    }

    // choice: groups 1-3 park acc in dead buffer smem, group 0 reduces
    float* Rch = (float*)sb4;             // 3 x [64][66] = 50,688 B < 81,920
    if (kg > 0) {
        float* Rg = Rch + (kg - 1) * 64 * 66;
        #pragma unroll
        for (int mt = 0; mt < 2; mt++) {
            const int rr = 32 * mw + 16 * mt + g;
            #pragma unroll
            for (int nt = 0; nt < 8; nt++) {
                const int col = nt * 8 + 2 * t;
                *(float2*)&Rg[rr * 66 + col]       = make_float2(acc[mt][nt][0], acc[mt][nt][1]);
                *(float2*)&Rg[(rr + 8) * 66 + col] = make_float2(acc[mt][nt][2], acc[mt][nt][3]);
            }
        }
    }
    __syncthreads();

    if (kg == 0) {
        float inv[4];
        #pragma unroll
        for (int mt = 0; mt < 2; mt++)
            #pragma unroll
            for (int i = 0; i < 2; i++) {
                const int row = 32 * mw + 16 * mt + g + 8 * i;
                float Z = Zp[row] + Zp[64 + row] + Zp[128 + row] + Zp[192 + row];
                inv[mt*2+i] = 1.0f / Z;
                if (t == 0)
                    out_v[r0 + row] =
                        (Vp[row] + Vp[64 + row] + Vp[128 + row] + Vp[192 + row]) / Z;
            }
        #pragma unroll
        for (int mt = 0; mt < 2; mt++) {
            const int rr = 32 * mw + 16 * mt + g;
            #pragma unroll
            for (int nt = 0; nt < 8; nt++) {
                const int col = nt * 8 + 2 * t;
                float s0 = acc[mt][nt][0], s1 = acc[mt][nt][1];
                float s2 = acc[mt][nt][2], s3 = acc[mt][nt][3];
                #pragma unroll
                for (int pg = 0; pg < 3; pg++) {
                    const float* Rg = Rch + pg * 64 * 66;
                    float2 p0 = *(const float2*)&Rg[rr * 66 + col];
                    float2 p1 = *(const float2*)&Rg[(rr + 8) * 66 + col];
                    s0 += p0.x; s1 += p0.y; s2 += p1.x; s3 += p1.y;
                }
                *(float2*)(out_choice + (size_t)(r0 + rr) * D_ + col) =
                    make_float2(s0 * inv[mt*2], s1 * inv[mt*2]);
                *(float2*)(out_choice + (size_t)(r0 + rr + 8) * D_ + col) =
                    make_float2(s2 * inv[mt*2+1], s3 * inv[mt*2+1]);
            }
        }
    }
}

// ---------------------------------------------------------------------------
extern "C" void kernel_launch(void* const* d_in, const int* in_sizes, int n_in,
                              void* d_out, int out_size) {
    const float* X    = (const float*)d_in[0];
    const float* Yw   = (const float*)d_in[1];
    const float* icpt = (const float*)d_in[2];
    float* out        = (float*)d_out;
    float* out_choice = out;
    float* out_v      = out + (size_t)S_ * D_;

    const int smemG = 2 * 128 * 36 * 16;          // 147,456
    const int smemS = 8 * 640 * 16 + 512 * 4;     // 83,968
    cudaFuncSetAttribute(k_gemm1_tc, cudaFuncAttributeMaxDynamicSharedMemorySize, smemG);
    cudaFuncSetAttribute(k_soft,     cudaFuncAttributeMaxDynamicSharedMemorySize, smemS);

    k_prepX<<<NX / 256, 256>>>(X);                          // launch 0
    k_prepY<<<(NYA + NYT) / 256, 256>>>(Yw);                // launch 1

    dim3 g1(K_ / 128, S_ / 128);
    k_gemm1_tc<<<g1, 256, smemG>>>(icpt);                   // launch 2
    k_soft<<<S_ / 64, 256, smemS>>>(out_choice, out_v);     // launch 3  <- ncu
}

// round 17
// speedup vs baseline: 1.6399x; 1.1493x over previous
#include <cuda_runtime.h>
#include <cuda_bf16.h>
#include <math_constants.h>
#include <cstdint>

#define S_ 16384
#define K_ 4096
#define D_ 64
#define TEMP_ 50.0f
#define MAXEFF_ 5000.0f

// ---------------- scratch ----------------
// aff in A-fragment-packed layout: [rb=S/16][cb=K/8][lane] float4,
// lane(g,t): {(16rb+g, 8cb+t), (g+8, t), (g, t+4), (g+8, t+4)}.
__device__ float4       g_affp[(size_t)(S_ / 16) * (K_ / 8) * 32];
__device__ unsigned int g_pmax[S_];   // max enc(aff); 0 == -inf (no init needed)
__device__ unsigned int g_nmax[S_];   // max enc(-aff)
// Fragment-packed tf32 splits {hi(t), hi(t+4), lo(t), lo(t+4)}:
__device__ float4 g_Xp[(size_t)S_ * 32];    // [row][d-slab][t]
__device__ float4 g_Yp1[K_ * 32];           // [row][d-slab][t]
__device__ float4 g_Yt2[D_ * (K_ / 8) * 4]; // [d][k-slab][t]

#define NX  (S_ * 32)
#define NYA (K_ * 32)
#define NYT (D_ * (K_ / 8) * 4)

__device__ __forceinline__ unsigned int encf(float f) {
    unsigned int u = __float_as_uint(f);
    return (u & 0x80000000u) ? ~u : (u | 0x80000000u);
}
__device__ __forceinline__ float decf(unsigned int u) {
    return (u & 0x80000000u) ? __uint_as_float(u ^ 0x80000000u)
                             : __uint_as_float(~u);
}
__device__ __forceinline__ float tf32r(float x) {
    uint32_t u;
    asm("cvt.rna.tf32.f32 %0, %1;" : "=r"(u) : "f"(x));
    return __uint_as_float(u);
}
__device__ __forceinline__ void split1(float x, float& h, float& l) {
    h = tf32r(x);
    l = tf32r(x - h);
}
__device__ __forceinline__ float ex2(float x) {
    float r; asm("ex2.approx.ftz.f32 %0, %1;" : "=f"(r) : "f"(x)); return r;
}
__device__ __forceinline__ void mma8(float* c, const uint32_t* a,
                                     uint32_t b0, uint32_t b1) {
    asm volatile(
        "mma.sync.aligned.m16n8k8.row.col.f32.tf32.tf32.f32 "
        "{%0,%1,%2,%3}, {%4,%5,%6,%7}, {%8,%9}, {%0,%1,%2,%3};"
        : "+f"(c[0]), "+f"(c[1]), "+f"(c[2]), "+f"(c[3])
        : "r"(a[0]), "r"(a[1]), "r"(a[2]), "r"(a[3]), "r"(b0), "r"(b1));
}

// ---------------------------------------------------------------------------
// k_prepX / k_prepY: packed split tables.
// ---------------------------------------------------------------------------
__global__ __launch_bounds__(256) void k_prepX(const float* __restrict__ X) {
    const int i = blockIdx.x * 256 + threadIdx.x;    // < NX
    int r = i >> 5, s = (i >> 2) & 7, t = i & 3;
    float h0, l0, h1, l1;
    split1(X[r * D_ + 8 * s + t],     h0, l0);
    split1(X[r * D_ + 8 * s + t + 4], h1, l1);
    g_Xp[i] = make_float4(h0, h1, l0, l1);
}
__global__ __launch_bounds__(256) void k_prepY(const float* __restrict__ Yw) {
    const int i = blockIdx.x * 256 + threadIdx.x;    // < NYA + NYT
    if (i < NYA) {
        int r = i >> 5, s = (i >> 2) & 7, t = i & 3;
        float h0, l0, h1, l1;
        split1(Yw[r * D_ + 8 * s + t],     h0, l0);
        split1(Yw[r * D_ + 8 * s + t + 4], h1, l1);
        g_Yp1[i] = make_float4(h0, h1, l0, l1);
    } else {
        int j = i - NYA;
        int d = j >> 11, s = (j >> 2) & 511, t = j & 3;
        float h0, l0, h1, l1;
        split1(Yw[(8 * s + t) * D_ + d],     h0, l0);
        split1(Yw[(8 * s + t + 4) * D_ + d], h1, l1);
        g_Yt2[j] = make_float4(h0, h1, l0, l1);
    }
}

// ---------------------------------------------------------------------------
// GEMM1: aff = X @ Y^T - icpt. CTA 128x128, 256 thr (R8 core).
// Epilogue: minimax atomics + SHUFFLE-based C-frag -> A-frag conversion,
// coalesced STG.128 into g_affp. No smem transpose, no extra barriers.
// ---------------------------------------------------------------------------
__global__ __launch_bounds__(256, 1) void k_gemm1_tc(const float* __restrict__ icpt)
{
    extern __shared__ float4 sm4[];
    float4* As = sm4;                 // [128][36]
    float4* Bs = sm4 + 128 * 36;      // [128][36]

    const int tid = threadIdx.x;
    const int lane = tid & 31, wid = tid >> 5;
    const int wrow = (wid & 3) * 32;
    const int wn = (wid >> 2) * 64;
    const int g = lane >> 2, t = lane & 3;
    const int r0 = blockIdx.y * 128, c0 = blockIdx.x * 128;

    #pragma unroll
    for (int j = 0; j < 16; j++) {
        int f = tid + j * 256;
        int row = f >> 5, w = f & 31;
        As[row * 36 + w] = g_Xp[(size_t)(r0 + row) * 32 + w];
        Bs[row * 36 + w] = g_Yp1[(c0 + row) * 32 + w];
    }
    __syncthreads();

    float acc[2][8][4];
    #pragma unroll
    for (int mt = 0; mt < 2; mt++)
        #pragma unroll
        for (int nt = 0; nt < 8; nt++)
            #pragma unroll
            for (int q = 0; q < 4; q++) acc[mt][nt][q] = 0.0f;

    #pragma unroll
    for (int s = 0; s < 8; s++) {
        uint32_t ah[2][4], al[2][4];
        #pragma unroll
        for (int mt = 0; mt < 2; mt++) {
            const int rb = wrow + mt * 16;
            uint4 q0 = *(const uint4*)&As[(rb + g) * 36 + s * 4 + t];
            uint4 q1 = *(const uint4*)&As[(rb + 8 + g) * 36 + s * 4 + t];
            ah[mt][0] = q0.x; ah[mt][1] = q1.x; ah[mt][2] = q0.y; ah[mt][3] = q1.y;
            al[mt][0] = q0.z; al[mt][1] = q1.z; al[mt][2] = q0.w; al[mt][3] = q1.w;
        }
        #pragma unroll
        for (int nt = 0; nt < 8; nt++) {
            uint4 bq = *(const uint4*)&Bs[(wn + nt * 8 + g) * 36 + s * 4 + t];
            #pragma unroll
            for (int mt = 0; mt < 2; mt++) {
                mma8(acc[mt][nt], ah[mt], bq.x, bq.y);
                mma8(acc[mt][nt], ah[mt], bq.z, bq.w);
                mma8(acc[mt][nt], al[mt], bq.x, bq.y);
            }
        }
    }

    // epilogue: -icpt, minimax, shuffle-pack, coalesced store
    float mx[4] = {-CUDART_INF_F, -CUDART_INF_F, -CUDART_INF_F, -CUDART_INF_F};
    float mn[4] = { CUDART_INF_F,  CUDART_INF_F,  CUDART_INF_F,  CUDART_INF_F};

    const int s1 = (lane & ~3) | (t >> 1);   // source lane for cols t
    const int s2 = s1 + 2;                   // source lane for cols t+4
    const bool odd = (t & 1);
    const int rbB = (r0 >> 4) + 2 * (wid & 3);        // + mt
    const int cbB = (c0 >> 3) + 8 * (wid >> 2);       // + nt

    #pragma unroll
    for (int mt = 0; mt < 2; mt++) {
        #pragma unroll
        for (int nt = 0; nt < 8; nt++) {
            const int c = c0 + wn + nt * 8 + 2 * t;
            float2 ic = __ldg((const float2*)(icpt + c));
            float o0 = acc[mt][nt][0] - ic.x;   // (g,   2t)
            float o1 = acc[mt][nt][1] - ic.y;   // (g,   2t+1)
            float o2 = acc[mt][nt][2] - ic.x;   // (g+8, 2t)
            float o3 = acc[mt][nt][3] - ic.y;   // (g+8, 2t+1)
            mx[mt*2]   = fmaxf(mx[mt*2],   fmaxf(o0, o1));
            mn[mt*2]   = fminf(mn[mt*2],   fminf(o0, o1));
            mx[mt*2+1] = fmaxf(mx[mt*2+1], fmaxf(o2, o3));
            mn[mt*2+1] = fminf(mn[mt*2+1], fminf(o2, o3));

            // C-frag -> A-frag permutation within the quad
            float a00 = __shfl_sync(0xffffffffu, o0, s1);
            float a01 = __shfl_sync(0xffffffffu, o1, s1);
            float a02 = __shfl_sync(0xffffffffu, o2, s1);
            float a03 = __shfl_sync(0xffffffffu, o3, s1);
            float b00 = __shfl_sync(0xffffffffu, o0, s2);
            float b01 = __shfl_sync(0xffffffffu, o1, s2);
            float b02 = __shfl_sync(0xffffffffu, o2, s2);
            float b03 = __shfl_sync(0xffffffffu, o3, s2);
            float4 outv;
            outv.x = odd ? a01 : a00;   // (g,   t)
            outv.y = odd ? a03 : a02;   // (g+8, t)
            outv.z = odd ? b01 : b00;   // (g,   t+4)
            outv.w = odd ? b03 : b02;   // (g+8, t+4)
            g_affp[((size_t)(rbB + mt) * (K_ / 8) + cbB + nt) * 32 + lane] = outv;
        }
    }
    #pragma unroll
    for (int m = 1; m < 4; m <<= 1) {
        #pragma unroll
        for (int i = 0; i < 4; i++) {
            mx[i] = fmaxf(mx[i], __shfl_xor_sync(0xffffffffu, mx[i], m));
            mn[i] = fminf(mn[i], __shfl_xor_sync(0xffffffffu, mn[i], m));
        }
    }
    if (t == 0) {
        #pragma unroll
        for (int mt = 0; mt < 2; mt++) {
            const int row = r0 + wrow + mt * 16 + g;
            atomicMax(&g_pmax[row],     encf(mx[mt*2]));
            atomicMax(&g_nmax[row],     encf(-mn[mt*2]));
            atomicMax(&g_pmax[row + 8], encf(mx[mt*2+1]));
            atomicMax(&g_nmax[row + 8], encf(-mn[mt*2+1]));
        }
    }
}

// ---------------------------------------------------------------------------
// k_soft: adaptive softmax + v + choice = w @ Y.
// 64-row CTAs (grid 256, 2 CTA/SM), 256 thr = 4 k-groups x 2 row-warps
// (32 rows/warp). A: coalesced LDG.128 frags from g_affp (1-step prefetch),
// exp in regs; e used at tf32-hi only (eh*yh + eh*yl; dropped el*y ~1e-4
// rel). z/v keep full fp32 e.
// ---------------------------------------------------------------------------
__global__ __launch_bounds__(256, 2) void k_soft(
    float* __restrict__ out_choice, float* __restrict__ out_v)
{
    extern __shared__ float4 sb4[];   // 8 bufs x [64 d][10 f4]  (81,920 B)
    float* Zp = (float*)(sb4 + 8 * 640);   // [4][64]
    float* Vp = Zp + 256;                  // [4][64]

    const int tid = threadIdx.x;
    const int lane = tid & 31, wid = tid >> 5;
    const int kg = wid >> 1;              // k-group 0..3
    const int mw = wid & 1;               // row-warp: rows 32*mw..
    const int g = lane >> 2, t = lane & 3;
    const int r0 = blockIdx.x * 64;
    const int rbase = (r0 >> 4) + 2 * mw; // global rb for mt=0

    float mr[4], cr[4];
    #pragma unroll
    for (int mt = 0; mt < 2; mt++)
        #pragma unroll
        for (int i = 0; i < 2; i++) {
            const int row = r0 + 32 * mw + 16 * mt + g + 8 * i;
            float mxv = decf(g_pmax[row]);
            float mnv = -decf(g_nmax[row]);
            float span = fmaxf(mxv - mnv, 1e-3f);
            float tr = fminf(fmaxf(TEMP_ / span, TEMP_), MAXEFF_);
            cr[mt*2+i] = tr * 1.4426950408889634f;
            mr[mt*2+i] = mxv;
        }

    float acc[2][8][4];
    #pragma unroll
    for (int mt = 0; mt < 2; mt++)
        #pragma unroll
        for (int nt = 0; nt < 8; nt++)
            #pragma unroll
            for (int q = 0; q < 4; q++) acc[mt][nt][q] = 0.0f;
    float zv[4] = {0, 0, 0, 0}, vv[4] = {0, 0, 0, 0};

    auto stage = [&](int R, int par) {
        #pragma unroll
        for (int j = 0; j < 8; j++) {
            int f = tid + j * 256;        // 0..2047
            int b = f >> 9, r = f & 511;
            int d = r >> 3, w = r & 7;
            sb4[(b * 2 + par) * 640 + d * 10 + w] =
                __ldg(&g_Yt2[d * 2048 + (4 * R + b) * 8 + w]);
        }
    };

    auto ldx = [&](int gstep, float4* xa) {
        const int c = 4 * (gstep >> 1) + kg;       // 16-k chunk
        const int cb = c * 2 + (gstep & 1);        // 8-col block
        #pragma unroll
        for (int mt = 0; mt < 2; mt++)
            xa[mt] = __ldg(&g_affp[((size_t)(rbase + mt) * (K_ / 8) + cb) * 32 + lane]);
    };

    stage(0, 0);
    float4 xa[2], xb[2];
    ldx(0, xa);
    __syncthreads();

    for (int R = 0; R < 64; R++) {
        const int par = R & 1;
        if (R + 1 < 64) stage(R + 1, par ^ 1);
        const float4* B = sb4 + (kg * 2 + par) * 640;

        #pragma unroll
        for (int s = 0; s < 2; s++) {
            const int gstep = R * 2 + s;
            if (gstep + 1 < 128) ldx(gstep + 1, xb);

            uint32_t ah[2][4];
            #pragma unroll
            for (int mt = 0; mt < 2; mt++) {
                float4 x = xa[mt];
                float e0 = ex2(fminf((x.x - mr[mt*2])   * cr[mt*2],   8.0f));
                float e1 = ex2(fminf((x.y - mr[mt*2+1]) * cr[mt*2+1], 8.0f));
                float e2 = ex2(fminf((x.z - mr[mt*2])   * cr[mt*2],   8.0f));
                float e3 = ex2(fminf((x.w - mr[mt*2+1]) * cr[mt*2+1], 8.0f));
                zv[mt*2]   += e0 + e2;
                zv[mt*2+1] += e1 + e3;
                vv[mt*2]   = fmaf(e0, x.x, fmaf(e2, x.z, vv[mt*2]));
                vv[mt*2+1] = fmaf(e1, x.y, fmaf(e3, x.w, vv[mt*2+1]));
                ah[mt][0] = __float_as_uint(tf32r(e0));
                ah[mt][1] = __float_as_uint(tf32r(e1));
                ah[mt][2] = __float_as_uint(tf32r(e2));
                ah[mt][3] = __float_as_uint(tf32r(e3));
            }
            #pragma unroll
            for (int nt = 0; nt < 8; nt++) {
                uint4 bq = *(const uint4*)&B[(nt * 8 + g) * 10 + s * 4 + t];
                #pragma unroll
                for (int mt = 0; mt < 2; mt++) {
                    mma8(acc[mt][nt], ah[mt], bq.x, bq.y);
                    mma8(acc[mt][nt], ah[mt], bq.z, bq.w);
                }
            }
            xa[0] = xb[0]; xa[1] = xb[1];
        }
        __syncthreads();
    }

    // z/v butterfly + park per-group partials
    #pragma unroll
    for (int m = 1; m < 4; m <<= 1) {
        #pragma unroll
        for (int i = 0; i < 4; i++) {
            zv[i] += __shfl_xor_sync(0xffffffffu, zv[i], m);
            vv[i] += __shfl_xor_sync(0xffffffffu, vv[i], m);
        }
    }
    if (t == 0) {
        #pragma unroll
        for (int mt = 0; mt < 2; mt++)
            #pragma unroll
            for (int i = 0; i < 2; i++) {
                const int row = 32 * mw + 16 * mt + g + 8 * i;
                Zp[kg * 64 + row] = zv[mt*2+i];
                Vp[kg * 64 + row] = vv[mt*2+i];
            }
    }

    // choice: groups 1-3 park acc in dead buffer smem, group 0 reduces
    float* Rch = (float*)sb4;             // 3 x [64][66] = 50,688 B < 81,920
    if (kg > 0) {
        float* Rg = Rch + (kg - 1) * 64 * 66;
        #pragma unroll
        for (int mt = 0; mt < 2; mt++) {
            const int rr = 32 * mw + 16 * mt + g;
            #pragma unroll
            for (int nt = 0; nt < 8; nt++) {
                const int col = nt * 8 + 2 * t;
                *(float2*)&Rg[rr * 66 + col]       = make_float2(acc[mt][nt][0], acc[mt][nt][1]);
                *(float2*)&Rg[(rr + 8) * 66 + col] = make_float2(acc[mt][nt][2], acc[mt][nt][3]);
            }
        }
    }
    __syncthreads();

    if (kg == 0) {
        float inv[4];
        #pragma unroll
        for (int mt = 0; mt < 2; mt++)
            #pragma unroll
            for (int i = 0; i < 2; i++) {
                const int row = 32 * mw + 16 * mt + g + 8 * i;
                float Z = Zp[row] + Zp[64 + row] + Zp[128 + row] + Zp[192 + row];
                inv[mt*2+i] = 1.0f / Z;
                if (t == 0)
                    out_v[r0 + row] =
                        (Vp[row] + Vp[64 + row] + Vp[128 + row] + Vp[192 + row]) / Z;
            }
        #pragma unroll
        for (int mt = 0; mt < 2; mt++) {
            const int rr = 32 * mw + 16 * mt + g;
            #pragma unroll
            for (int nt = 0; nt < 8; nt++) {
                const int col = nt * 8 + 2 * t;
                float s0 = acc[mt][nt][0], s1 = acc[mt][nt][1];
                float s2 = acc[mt][nt][2], s3 = acc[mt][nt][3];
                #pragma unroll
                for (int pg = 0; pg < 3; pg++) {
                    const float* Rg = Rch + pg * 64 * 66;
                    float2 p0 = *(const float2*)&Rg[rr * 66 + col];
                    float2 p1 = *(const float2*)&Rg[(rr + 8) * 66 + col];
                    s0 += p0.x; s1 += p0.y; s2 += p1.x; s3 += p1.y;
                }
                *(float2*)(out_choice + (size_t)(r0 + rr) * D_ + col) =
                    make_float2(s0 * inv[mt*2], s1 * inv[mt*2]);
                *(float2*)(out_choice + (size_t)(r0 + rr + 8) * D_ + col) =
                    make_float2(s2 * inv[mt*2+1], s3 * inv[mt*2+1]);
            }
        }
    }
}

// ---------------------------------------------------------------------------
extern "C" void kernel_launch(void* const* d_in, const int* in_sizes, int n_in,
                              void* d_out, int out_size) {
    const float* X    = (const float*)d_in[0];
    const float* Yw   = (const float*)d_in[1];
    const float* icpt = (const float*)d_in[2];
    float* out        = (float*)d_out;
    float* out_choice = out;
    float* out_v      = out + (size_t)S_ * D_;

    const int smemG = 2 * 128 * 36 * 16;          // 147,456
    const int smemS = 8 * 640 * 16 + 512 * 4;     // 83,968
    cudaFuncSetAttribute(k_gemm1_tc, cudaFuncAttributeMaxDynamicSharedMemorySize, smemG);
    cudaFuncSetAttribute(k_soft,     cudaFuncAttributeMaxDynamicSharedMemorySize, smemS);

    k_prepX<<<NX / 256, 256>>>(X);                          // launch 0
    k_prepY<<<(NYA + NYT) / 256, 256>>>(Yw);                // launch 1

    dim3 g1(K_ / 128, S_ / 128);
    k_gemm1_tc<<<g1, 256, smemG>>>(icpt);                   // launch 2
    k_soft<<<S_ / 64, 256, smemS>>>(out_choice, out_v);     // launch 3  <- ncu
}